// round 2
// baseline (speedup 1.0000x reference)
#include <cuda_runtime.h>
#include <cuda_bf16.h>

#define N_NODES 50000
#define N_EDGES 800000
#define D 64

// Scratch (device globals — no allocation allowed in kernel_launch)
__device__ __align__(16) float g_M[(size_t)N_NODES * D];  // relu(h @ W_h + b_h), 12.8 MB
__device__ float g_w[N_NODES];                            // relu(h @ W_x + b_x)
__device__ int   g_idx_is64;                              // edge_index dtype flag

// ---------------------------------------------------------------------------
// Kernel 0: detect edge_index dtype. jax.random.randint(dtype=int64) silently
// yields int32 unless x64 is enabled. If the buffer is real int64 (values in
// [0, 50000)), every odd int32 word is the zero high-half; if it is int32,
// odd words are actual random edge values. Deterministic on fixed inputs.
// ---------------------------------------------------------------------------
__global__ void detect_kernel(const int* __restrict__ ei32)
{
    if (threadIdx.x == 0) {
        int is64 = 1;
        for (int i = 1; i < 128; i += 2)
            if (ei32[i] != 0) { is64 = 0; break; }
        g_idx_is64 = is64;
    }
}

// ---------------------------------------------------------------------------
// Kernel 1: per-node precompute + output init.
// One warp per node. W_h staged in shared [k][d]; h row held in 2 regs/lane,
// broadcast via shfl. Also writes h_out = h, x_out = x (d_out is poisoned).
// ---------------------------------------------------------------------------
__global__ __launch_bounds__(256) void node_kernel(
    const float* __restrict__ h, const float* __restrict__ x,
    const float* __restrict__ W_h, const float* __restrict__ b_h,
    const float* __restrict__ W_x, const float* __restrict__ b_x,
    float* __restrict__ h_out, float* __restrict__ x_out)
{
    __shared__ float Ws[D][D];   // Ws[k][d] = W_h[k*D + d]
    __shared__ float Wxs[D];
    __shared__ float bhs[D];

    int tid = threadIdx.x;
    for (int i = tid; i < D * D; i += blockDim.x)
        Ws[i >> 6][i & 63] = W_h[i];
    if (tid < D) { Wxs[tid] = W_x[tid]; bhs[tid] = b_h[tid]; }
    __syncthreads();

    int warp = tid >> 5, lane = tid & 31;
    int node = blockIdx.x * (blockDim.x >> 5) + warp;
    if (node >= N_NODES) return;

    const float* hr = h + (size_t)node * D;
    float h0 = hr[lane];
    float h1 = hr[lane + 32];

    float m0 = 0.f, m1 = 0.f;
#pragma unroll
    for (int k = 0; k < 32; k++) {
        float hk = __shfl_sync(0xffffffffu, h0, k);
        m0 = fmaf(hk, Ws[k][lane], m0);
        m1 = fmaf(hk, Ws[k][lane + 32], m1);
    }
#pragma unroll
    for (int k = 0; k < 32; k++) {
        float hk = __shfl_sync(0xffffffffu, h1, k);
        m0 = fmaf(hk, Ws[k + 32][lane], m0);
        m1 = fmaf(hk, Ws[k + 32][lane + 32], m1);
    }
    m0 = fmaxf(m0 + bhs[lane], 0.f);
    m1 = fmaxf(m1 + bhs[lane + 32], 0.f);
    g_M[(size_t)node * D + lane]      = m0;
    g_M[(size_t)node * D + lane + 32] = m1;

    // per-node edge weight = relu(h . W_x + b_x)
    float wacc = fmaf(h0, Wxs[lane], h1 * Wxs[lane + 32]);
#pragma unroll
    for (int o = 16; o > 0; o >>= 1)
        wacc += __shfl_xor_sync(0xffffffffu, wacc, o);
    if (lane == 0) g_w[node] = fmaxf(wacc + b_x[0], 0.f);

    // init outputs (accumulation targets)
    h_out[(size_t)node * D + lane]      = h0;
    h_out[(size_t)node * D + lane + 32] = h1;
    if (lane < 3) x_out[node * 3 + lane] = x[node * 3 + lane];
}

// ---------------------------------------------------------------------------
// Kernel 2: edge scatter. 16 threads per edge; each thread moves one float4
// of M[col] into h_out[row] via a vector reduction (red.global.add.v4.f32,
// sm_90+), quartering the L2 atomic-op count vs scalar atomicAdd.
// Thread 0 of each edge also handles the 3-float weighted delta_x scatter.
// ---------------------------------------------------------------------------
__device__ __forceinline__ void red_add_v4(float* addr, float4 v) {
    asm volatile("red.global.add.v4.f32 [%0], {%1, %2, %3, %4};"
                 :: "l"(addr), "f"(v.x), "f"(v.y), "f"(v.z), "f"(v.w)
                 : "memory");
}

#define EPB 16  // edges per block (256 threads / 16 threads-per-edge)

__global__ __launch_bounds__(256) void edge_kernel(
    const void* __restrict__ ei_raw,    // [2, N_EDGES] int32 OR int64
    const float* __restrict__ x,
    float* __restrict__ h_out, float* __restrict__ x_out)
{
    __shared__ int s_row[EPB], s_col[EPB];
    int e0 = blockIdx.x * EPB;
    int tid = threadIdx.x;

    int is64 = g_idx_is64;
    if (tid < 2 * EPB) {
        int which = tid >= EPB;                 // 0 = row slot, 1 = col slot
        int le    = which ? (tid - EPB) : tid;
        int e     = e0 + le;
        int v = 0;
        if (e < N_EDGES) {
            size_t idx = (size_t)which * N_EDGES + e;
            if (is64) v = (int)((const long long*)ei_raw)[idx];
            else      v = ((const int*)ei_raw)[idx];
        }
        if (which) s_col[le] = v; else s_row[le] = v;
    }
    __syncthreads();

    int le = tid >> 4;        // local edge 0..15
    int c  = tid & 15;        // float4 chunk 0..15
    int e  = e0 + le;
    if (e >= N_EDGES) return;

    int row = s_row[le];
    int col = s_col[le];

    float4 mv = *(const float4*)(g_M + (size_t)col * D + (size_t)c * 4);
    red_add_v4(h_out + (size_t)row * D + (size_t)c * 4, mv);

    if (c == 0) {
        float w = g_w[col];
        const float* xr = x + (size_t)row * 3;
        const float* xc = x + (size_t)col * 3;
        atomicAdd(x_out + (size_t)row * 3 + 0, (xr[0] - xc[0]) * w);
        atomicAdd(x_out + (size_t)row * 3 + 1, (xr[1] - xc[1]) * w);
        atomicAdd(x_out + (size_t)row * 3 + 2, (xr[2] - xc[2]) * w);
    }
}

// ---------------------------------------------------------------------------
extern "C" void kernel_launch(void* const* d_in, const int* in_sizes, int n_in,
                              void* d_out, int out_size)
{
    const float* h   = (const float*)d_in[0];       // [50000, 64]
    const float* x   = (const float*)d_in[1];       // [50000, 3]
    const void*  ei  = d_in[2];                     // [2, 800000] int32 or int64
    const float* W_h = (const float*)d_in[3];       // [64, 64]
    const float* b_h = (const float*)d_in[4];       // [64]
    const float* W_x = (const float*)d_in[5];       // [64, 1]
    const float* b_x = (const float*)d_in[6];       // [1]

    float* h_out = (float*)d_out;                         // first 50000*64
    float* x_out = (float*)d_out + (size_t)N_NODES * D;   // then 50000*3

    // Kernel 0: resolve edge_index dtype (int32 vs int64)
    detect_kernel<<<1, 32>>>((const int*)ei);

    // Kernel 1: 8 warps/block -> 8 nodes/block
    int nodes_per_block = 256 / 32;
    int nblocks = (N_NODES + nodes_per_block - 1) / nodes_per_block;
    node_kernel<<<nblocks, 256>>>(h, x, W_h, b_h, W_x, b_x, h_out, x_out);

    // Kernel 2: 16 edges/block
    int eblocks = (N_EDGES + EPB - 1) / EPB;
    edge_kernel<<<eblocks, 256>>>(ei, x, h_out, x_out);
}

// round 3
// speedup vs baseline: 1.2491x; 1.2491x over previous
#include <cuda_runtime.h>
#include <cuda_bf16.h>

#define N_NODES 50000
#define N_EDGES 800000
#define D 64
#define CAP 128   // bucket capacity per node; P(deg>=128 | Poisson(16)) < 1e-60

// Scratch (device globals — no allocation allowed in kernel_launch)
__device__ __align__(16) float g_M[(size_t)N_NODES * D]; // relu(h @ W_h + b_h), 12.8 MB
__device__ float g_w[N_NODES];                           // relu(h @ W_x + b_x)
__device__ int   g_cnt[N_NODES];                         // per-dest edge count / cursor
__device__ int   g_bucket[(size_t)N_NODES * CAP];        // source node per dest slot, 25.6 MB
__device__ int   g_idx_is64;                             // edge_index dtype flag

// ---------------------------------------------------------------------------
// Kernel 0: zero counts + detect edge_index dtype.
// jax.random.randint(dtype=int64) silently yields int32 without x64 mode.
// Real int64 values < 50000 => every odd int32 word is a zero high-half;
// int32 data has random values there (P[all 64 zero | int32] ~ 0).
// ---------------------------------------------------------------------------
__global__ __launch_bounds__(256) void init_kernel(const int* __restrict__ ei32)
{
    int i = blockIdx.x * blockDim.x + threadIdx.x;
    if (i < N_NODES) g_cnt[i] = 0;
    if (blockIdx.x == 0 && threadIdx.x < 32) {
        int odd = ei32[2 * threadIdx.x + 1];
        unsigned nz = __ballot_sync(0xffffffffu, odd != 0);
        if (threadIdx.x == 0) g_idx_is64 = (nz == 0u);
    }
}

// ---------------------------------------------------------------------------
// Kernel 1: per-node precompute. One warp per node: M = relu(h @ W_h + b_h),
// w = relu(h . W_x + b_x). W_h staged in shared; h broadcast via shfl.
// ---------------------------------------------------------------------------
__global__ __launch_bounds__(256) void node_kernel(
    const float* __restrict__ h,
    const float* __restrict__ W_h, const float* __restrict__ b_h,
    const float* __restrict__ W_x, const float* __restrict__ b_x)
{
    __shared__ float Ws[D][D];   // Ws[k][d]
    __shared__ float Wxs[D];
    __shared__ float bhs[D];

    int tid = threadIdx.x;
    for (int i = tid; i < D * D; i += blockDim.x)
        Ws[i >> 6][i & 63] = W_h[i];
    if (tid < D) { Wxs[tid] = W_x[tid]; bhs[tid] = b_h[tid]; }
    __syncthreads();

    int warp = tid >> 5, lane = tid & 31;
    int node = blockIdx.x * (blockDim.x >> 5) + warp;
    if (node >= N_NODES) return;

    const float* hr = h + (size_t)node * D;
    float h0 = hr[lane];
    float h1 = hr[lane + 32];

    float m0 = 0.f, m1 = 0.f;
#pragma unroll
    for (int k = 0; k < 32; k++) {
        float hk = __shfl_sync(0xffffffffu, h0, k);
        m0 = fmaf(hk, Ws[k][lane], m0);
        m1 = fmaf(hk, Ws[k][lane + 32], m1);
    }
#pragma unroll
    for (int k = 0; k < 32; k++) {
        float hk = __shfl_sync(0xffffffffu, h1, k);
        m0 = fmaf(hk, Ws[k + 32][lane], m0);
        m1 = fmaf(hk, Ws[k + 32][lane + 32], m1);
    }
    g_M[(size_t)node * D + lane]      = fmaxf(m0 + bhs[lane], 0.f);
    g_M[(size_t)node * D + lane + 32] = fmaxf(m1 + bhs[lane + 32], 0.f);

    float wacc = fmaf(h0, Wxs[lane], h1 * Wxs[lane + 32]);
#pragma unroll
    for (int o = 16; o > 0; o >>= 1)
        wacc += __shfl_xor_sync(0xffffffffu, wacc, o);
    if (lane == 0) g_w[node] = fmaxf(wacc + b_x[0], 0.f);
}

// ---------------------------------------------------------------------------
// Kernel 2: bucket edges by destination. Thread per edge: pos = cnt[row]++,
// bucket[row][pos] = col. Only INT atomics (spread over 50000 addrs).
// ---------------------------------------------------------------------------
__global__ __launch_bounds__(256) void scatter_kernel(const void* __restrict__ ei_raw)
{
    int e = blockIdx.x * blockDim.x + threadIdx.x;
    if (e >= N_EDGES) return;
    int row, col;
    if (g_idx_is64) {
        row = (int)((const long long*)ei_raw)[e];
        col = (int)((const long long*)ei_raw)[(size_t)N_EDGES + e];
    } else {
        row = ((const int*)ei_raw)[e];
        col = ((const int*)ei_raw)[(size_t)N_EDGES + e];
    }
    int pos = atomicAdd(&g_cnt[row], 1);
    if (pos < CAP) g_bucket[(size_t)row * CAP + pos] = col;
}

// ---------------------------------------------------------------------------
// Kernel 3: atomic-free aggregation. One warp per node; each lane holds one
// float2 of the 64-float accumulator (32 x 2 = 64). Per edge: one coalesced
// LDG.64 of M[col] per lane; 4-deep batching for MLP. Lanes 0..2 accumulate
// the weighted delta_x. Single write of h_out/x_out (also serves as init).
// ---------------------------------------------------------------------------
__global__ __launch_bounds__(256) void agg_kernel(
    const float* __restrict__ h, const float* __restrict__ x,
    float* __restrict__ h_out, float* __restrict__ x_out)
{
    int warp = threadIdx.x >> 5, lane = threadIdx.x & 31;
    int node = blockIdx.x * (blockDim.x >> 5) + warp;
    if (node >= N_NODES) return;

    int deg = g_cnt[node];
    if (deg > CAP) deg = CAP;
    const int* bk = g_bucket + (size_t)node * CAP;

    float xr = (lane < 3) ? x[(size_t)node * 3 + lane] : 0.f;
    float2 acc = make_float2(0.f, 0.f);
    float ax = 0.f;

    for (int base = 0; base < deg; base += 32) {
        int n = deg - base; if (n > 32) n = 32;
        int colv = (base + lane < deg) ? bk[base + lane] : 0;

        int j = 0;
        for (; j + 4 <= n; j += 4) {
            int c0 = __shfl_sync(0xffffffffu, colv, j);
            int c1 = __shfl_sync(0xffffffffu, colv, j + 1);
            int c2 = __shfl_sync(0xffffffffu, colv, j + 2);
            int c3 = __shfl_sync(0xffffffffu, colv, j + 3);
            float2 m0 = ((const float2*)(g_M + (size_t)c0 * D))[lane];
            float2 m1 = ((const float2*)(g_M + (size_t)c1 * D))[lane];
            float2 m2 = ((const float2*)(g_M + (size_t)c2 * D))[lane];
            float2 m3 = ((const float2*)(g_M + (size_t)c3 * D))[lane];
            acc.x += m0.x + m1.x + m2.x + m3.x;
            acc.y += m0.y + m1.y + m2.y + m3.y;
            if (lane < 3) {
                float w0 = g_w[c0], w1 = g_w[c1], w2 = g_w[c2], w3 = g_w[c3];
                float x0 = x[(size_t)c0 * 3 + lane], x1 = x[(size_t)c1 * 3 + lane];
                float x2 = x[(size_t)c2 * 3 + lane], x3 = x[(size_t)c3 * 3 + lane];
                ax += w0 * (xr - x0) + w1 * (xr - x1) + w2 * (xr - x2) + w3 * (xr - x3);
            }
        }
        for (; j < n; j++) {
            int c = __shfl_sync(0xffffffffu, colv, j);
            float2 m = ((const float2*)(g_M + (size_t)c * D))[lane];
            acc.x += m.x; acc.y += m.y;
            if (lane < 3)
                ax += g_w[c] * (xr - x[(size_t)c * 3 + lane]);
        }
    }

    float2 hv = ((const float2*)(h + (size_t)node * D))[lane];
    float2 out = make_float2(hv.x + acc.x, hv.y + acc.y);
    ((float2*)(h_out + (size_t)node * D))[lane] = out;
    if (lane < 3) x_out[(size_t)node * 3 + lane] = xr + ax;
}

// ---------------------------------------------------------------------------
extern "C" void kernel_launch(void* const* d_in, const int* in_sizes, int n_in,
                              void* d_out, int out_size)
{
    const float* h   = (const float*)d_in[0];       // [50000, 64]
    const float* x   = (const float*)d_in[1];       // [50000, 3]
    const void*  ei  = d_in[2];                     // [2, 800000] int32-or-int64
    const float* W_h = (const float*)d_in[3];       // [64, 64]
    const float* b_h = (const float*)d_in[4];       // [64]
    const float* W_x = (const float*)d_in[5];       // [64, 1]
    const float* b_x = (const float*)d_in[6];       // [1]

    float* h_out = (float*)d_out;                         // first 50000*64
    float* x_out = (float*)d_out + (size_t)N_NODES * D;   // then 50000*3

    init_kernel<<<(N_NODES + 255) / 256, 256>>>((const int*)ei);

    int nodes_per_block = 256 / 32;
    int nblocks = (N_NODES + nodes_per_block - 1) / nodes_per_block;
    node_kernel<<<nblocks, 256>>>(h, W_h, b_h, W_x, b_x);

    scatter_kernel<<<(N_EDGES + 255) / 256, 256>>>(ei);

    agg_kernel<<<nblocks, 256>>>(h, x, h_out, x_out);
}